// round 2
// baseline (speedup 1.0000x reference)
#include <cuda_runtime.h>
#include <cstddef>

#define B    16
#define NT   64
#define LN   256
#define LV   4
#define DIM  256
#define VOC  32000
#define MM   128
#define LS   4

// ---------------- scratch (device globals; no allocation) ----------------
__device__ __align__(16) float g_roots[B*NT*DIM];   // 1 MB
__device__ __align__(16) float g_kv  [B*DIM];
__device__ __align__(16) float g_hnew[B*DIM];
__device__ __align__(16) float g_u   [B*DIM];
__device__ __align__(16) float g_x512[B*2*DIM];     // [u | o0] per b
__device__ __align__(16) float g_M   [4*B*MM*DIM];  // 8 MB: sum_s C[k][story]

__device__ __forceinline__ float warp_sum(float v) {
    #pragma unroll
    for (int o = 16; o; o >>= 1) v += __shfl_xor_sync(0xffffffffu, v, o);
    return v;
}
__device__ __forceinline__ float warp_max(float v) {
    #pragma unroll
    for (int o = 16; o; o >>= 1) v = fmaxf(v, __shfl_xor_sync(0xffffffffu, v, o));
    return v;
}

// ---------------- kernel A: q, kv, GRU (per-b) ----------------
__global__ __launch_bounds__(256) void kA(
    const int* __restrict__ dec, const float* __restrict__ hidden,
    const float* __restrict__ C, const float* __restrict__ Wq,
    const float* __restrict__ Wk, const float* __restrict__ W_ih,
    const float* __restrict__ W_hh, const float* __restrict__ b_ih,
    const float* __restrict__ b_hh, float* __restrict__ out_hnew)
{
    int b = blockIdx.x, t = threadIdx.x;
    int w = t >> 5, lane = t & 31;
    __shared__ float sh_x[DIM], sh_h[DIM], sh_q[DIM], sh_gi[3*DIM], sh_gh[3*DIM];

    sh_h[t] = hidden[b*DIM + t];
    sh_x[t] = C[(size_t)dec[b]*DIM + t];   // C0 row
    __syncthreads();

    // q[k] = sum_j h[j]*Wq[k,j]
    for (int k = w; k < DIM; k += 8) {
        float s = 0.f;
        for (int j = lane; j < DIM; j += 32) s += Wq[k*DIM + j] * sh_h[j];
        s = warp_sum(s);
        if (lane == 0) sh_q[k] = s;
    }
    // gi = x@W_ih.T + b_ih ; gh = h@W_hh.T + b_hh
    for (int k = w; k < 3*DIM; k += 8) {
        float s = 0.f;
        for (int j = lane; j < DIM; j += 32) s += W_ih[k*DIM + j] * sh_x[j];
        s = warp_sum(s);
        if (lane == 0) sh_gi[k] = s + b_ih[k];
    }
    for (int k = w; k < 3*DIM; k += 8) {
        float s = 0.f;
        for (int j = lane; j < DIM; j += 32) s += W_hh[k*DIM + j] * sh_h[j];
        s = warp_sum(s);
        if (lane == 0) sh_gh[k] = s + b_hh[k];
    }
    __syncthreads();

    // kv[d] = sum_k Wk[k,d]*q[k]   (coalesced over d)
    float kv = 0.f;
    for (int k = 0; k < DIM; k++) kv += Wk[k*DIM + t] * sh_q[k];
    g_kv[b*DIM + t] = kv;

    float r  = 1.f / (1.f + __expf(-(sh_gi[t]        + sh_gh[t])));
    float z  = 1.f / (1.f + __expf(-(sh_gi[DIM+t]    + sh_gh[DIM+t])));
    float n  = tanhf(sh_gi[2*DIM+t] + r * sh_gh[2*DIM+t]);
    float hn = (1.f - z) * n + z * sh_h[t];
    g_hnew[b*DIM + t] = hn;
    out_hnew[b*DIM + t] = hn;
}

// ---------------- kernel B: roots (the heavy gather) ----------------
__global__ __launch_bounds__(256) void kB(
    const int* __restrict__ kb_values, const int* __restrict__ kb_types,
    const float* __restrict__ C, const float* __restrict__ T_emb)
{
    __shared__ __align__(16) int s_vals[LN*LV];
    __shared__ int s_types[LN];
    __shared__ float4 s_part[3*64];

    int bn = blockIdx.x;           // b*NT + n
    int t  = threadIdx.x;
    int g  = t >> 6;               // l-subgroup 0..3
    int c  = t & 63;               // float4 column

    const int* vp = kb_values + (size_t)bn * LN * LV;
    for (int i = t; i < LN*LV; i += 256) s_vals[i] = vp[i];
    s_types[t] = kb_types[(size_t)bn*LN + t];
    __syncthreads();

    const float4* C0 = (const float4*)C;
    const float4* TE = (const float4*)T_emb;
    float4 acc = make_float4(0.f, 0.f, 0.f, 0.f);

    for (int l = g; l < LN; l += 4) {
        int4 vv = *(const int4*)&s_vals[l*4];
        int  ty = s_types[l];
        float4 te = TE[(size_t)ty*64 + c];
        float4 a0 = C0[(size_t)vv.x*64 + c];
        float4 a1 = C0[(size_t)vv.y*64 + c];
        float4 a2 = C0[(size_t)vv.z*64 + c];
        float4 a3 = C0[(size_t)vv.w*64 + c];
        float sx = (a0.x + a1.x) + (a2.x + a3.x);
        float sy = (a0.y + a1.y) + (a2.y + a3.y);
        float sz = (a0.z + a1.z) + (a2.z + a3.z);
        float sw = (a0.w + a1.w) + (a2.w + a3.w);
        acc.x += te.x * sx;
        acc.y += te.y * sy;
        acc.z += te.z * sz;
        acc.w += te.w * sw;
    }
    if (g) s_part[(g-1)*64 + c] = acc;
    __syncthreads();
    if (!g) {
        float4 p0 = s_part[c], p1 = s_part[64+c], p2 = s_part[128+c];
        acc.x += p0.x + p1.x + p2.x;
        acc.y += p0.y + p1.y + p2.y;
        acc.z += p0.z + p1.z + p2.z;
        acc.w += p0.w + p1.w + p2.w;
        *(float4*)&g_roots[((size_t)bn*64 + c)*4] = acc;
    }
}

// ---------------- kernel C: attention over roots -> feat, u ----------------
__global__ __launch_bounds__(256) void kC(const float* __restrict__ Wv)
{
    int b = blockIdx.x, t = threadIdx.x;
    int w = t >> 5, lane = t & 31;
    __shared__ float s_sc[NT], s_rbar[DIM], s_feat[DIM], s_kv[DIM];

    s_kv[t] = g_kv[b*DIM + t];
    __syncthreads();

    // scores + bias (warp per n)
    for (int n = w; n < NT; n += 8) {
        const float* r = g_roots + ((size_t)b*NT + n)*DIM;
        float sc = 0.f, rs = 0.f;
        for (int j = lane; j < DIM; j += 32) { float rv = r[j]; sc += rv * s_kv[j]; rs += rv; }
        sc = warp_sum(sc);
        rs = warp_sum(rs);
        if (lane == 0) s_sc[n] = (rs == 0.0f) ? sc - 1e9f : sc;
    }
    __syncthreads();

    if (t < 32) {  // softmax over 64 with one warp (2 per lane)
        float a = fmaxf(s_sc[t], s_sc[t+32]);
        a = warp_max(a);
        float e0 = __expf(s_sc[t] - a), e1 = __expf(s_sc[t+32] - a);
        float sm = warp_sum(e0 + e1);
        float inv = 1.f / sm;
        s_sc[t] = e0 * inv; s_sc[t+32] = e1 * inv;
    }
    __syncthreads();

    float rb = 0.f;
    for (int n = 0; n < NT; n++) rb += s_sc[n] * g_roots[((size_t)b*NT + n)*DIM + t];
    s_rbar[t] = rb;
    __syncthreads();

    // feat = rbar @ Wv.T (warp per row)
    for (int k = w; k < DIM; k += 8) {
        float s = 0.f;
        for (int j = lane; j < DIM; j += 32) s += Wv[k*DIM + j] * s_rbar[j];
        s = warp_sum(s);
        if (lane == 0) s_feat[k] = s;
    }
    __syncthreads();

    float u = g_hnew[b*DIM + t] + s_feat[t];
    g_u[b*DIM + t]   = u;
    g_x512[b*2*DIM + t] = u;   // first half of concat input for p_vocab
}

// ---------------- kernel D: M_k[b,m] = sum_s C[k][story[b,m,s]] ----------------
__global__ __launch_bounds__(64) void kD(const int* __restrict__ story, const float* __restrict__ C)
{
    int bm = blockIdx.x;       // b*MM + m
    int c  = threadIdx.x;      // 0..63 (float4 col)
    const int* st = story + (size_t)bm*LS;
    int i0 = st[0], i1 = st[1], i2 = st[2], i3 = st[3];
    const float4* Cf = (const float4*)C;
    float4* Mf = (float4*)g_M;
    #pragma unroll
    for (int k = 0; k < 4; k++) {
        const float4* Ck = Cf + (size_t)k * VOC * (DIM/4);
        float4 a = Ck[(size_t)i0*64 + c];
        float4 b4 = Ck[(size_t)i1*64 + c];
        float4 c4 = Ck[(size_t)i2*64 + c];
        float4 d4 = Ck[(size_t)i3*64 + c];
        float4 r;
        r.x = (a.x + b4.x) + (c4.x + d4.x);
        r.y = (a.y + b4.y) + (c4.y + d4.y);
        r.z = (a.z + b4.z) + (c4.z + d4.z);
        r.w = (a.w + b4.w) + (c4.w + d4.w);
        Mf[((size_t)k*B*MM + bm)*64 + c] = r;
    }
}

// ---------------- kernel E: 3 memory hops ----------------
__global__ __launch_bounds__(256) void kE(float* __restrict__ out_pptr)
{
    int b = blockIdx.x, t = threadIdx.x;
    int w = t >> 5, lane = t & 31;
    __shared__ float s_u[DIM], s_l[MM];
    __shared__ float s_inv;

    s_u[t] = g_u[b*DIM + t];
    __syncthreads();

    for (int hop = 0; hop < 3; hop++) {
        const float* MA = g_M + ((size_t)hop*B + b) * MM * DIM;
        for (int m = w; m < MM; m += 8) {
            const float* row = MA + (size_t)m*DIM;
            float s = 0.f;
            for (int j = lane; j < DIM; j += 32) s += row[j] * s_u[j];
            s = warp_sum(s);
            if (lane == 0) s_l[m] = s;
        }
        __syncthreads();

        if (hop == 2) {                       // p_ptr = raw logits of last hop
            if (t < MM) out_pptr[b*MM + t] = s_l[t];
            return;
        }

        if (t < 32) {                          // softmax over 128 (4 per lane)
            float a = -1e30f, e[4];
            #pragma unroll
            for (int q = 0; q < 4; q++) a = fmaxf(a, s_l[t + 32*q]);
            a = warp_max(a);
            float sm = 0.f;
            #pragma unroll
            for (int q = 0; q < 4; q++) { e[q] = __expf(s_l[t + 32*q] - a); sm += e[q]; }
            sm = warp_sum(sm);
            #pragma unroll
            for (int q = 0; q < 4; q++) s_l[t + 32*q] = e[q];
            if (t == 0) s_inv = 1.f / sm;
        }
        __syncthreads();

        const float* MC = g_M + ((size_t)(hop+1)*B + b) * MM * DIM;
        float o = 0.f;
        for (int m = 0; m < MM; m++) o += s_l[m] * MC[(size_t)m*DIM + t];
        o *= s_inv;
        if (hop == 0) g_x512[b*2*DIM + DIM + t] = o;   // second half of concat
        __syncthreads();
        s_u[t] += o;
        __syncthreads();
    }
}

// ---------------- kernel F: p_vocab = [u|o] @ W1_w.T + b ----------------
__global__ __launch_bounds__(256) void kF(
    const float* __restrict__ W1w, const float* __restrict__ W1b,
    float* __restrict__ out_pv)
{
    __shared__ float W_s[256*33];   // [v_local][j] stride 33 (conflict-free)
    __shared__ float x_s[32*16];    // [j][b]

    int t = threadIdx.x;
    int vblk = blockIdx.x * 256;
    int bg = t & 3;                 // b group (4 b's each)
    int vg = t >> 2;                // 0..63 (4 v's each)
    int ljq = t & 7, lvb = t >> 3;  // loader mapping

    float acc[16];
    #pragma unroll
    for (int i = 0; i < 16; i++) acc[i] = 0.f;

    for (int ch = 0; ch < 16; ch++) {
        int j0 = ch * 32;
        // stage W tile (coalesced LDG.128, conflict-free scalar STS)
        #pragma unroll
        for (int v = lvb; v < 256; v += 32) {
            float4 gw = *(const float4*)&W1w[(size_t)(vblk + v)*512 + j0 + ljq*4];
            int base = v*33 + ljq*4;
            W_s[base+0] = gw.x; W_s[base+1] = gw.y;
            W_s[base+2] = gw.z; W_s[base+3] = gw.w;
        }
        // stage x tile (tiny; conflict-free STS)
        {
            int i = t;
            #pragma unroll
            for (int rep = 0; rep < 2; rep++, i += 256) {
                int jj = i >> 4, bb = i & 15;
                x_s[jj*16 + bb] = g_x512[bb*2*DIM + j0 + jj];
            }
        }
        __syncthreads();

        #pragma unroll
        for (int j = 0; j < 32; j++) {
            float4 xv = *(const float4*)&x_s[j*16 + bg*4];
            float w0 = W_s[(vg*4+0)*33 + j];
            float w1 = W_s[(vg*4+1)*33 + j];
            float w2 = W_s[(vg*4+2)*33 + j];
            float w3 = W_s[(vg*4+3)*33 + j];
            acc[ 0] += w0*xv.x; acc[ 1] += w0*xv.y; acc[ 2] += w0*xv.z; acc[ 3] += w0*xv.w;
            acc[ 4] += w1*xv.x; acc[ 5] += w1*xv.y; acc[ 6] += w1*xv.z; acc[ 7] += w1*xv.w;
            acc[ 8] += w2*xv.x; acc[ 9] += w2*xv.y; acc[10] += w2*xv.z; acc[11] += w2*xv.w;
            acc[12] += w3*xv.x; acc[13] += w3*xv.y; acc[14] += w3*xv.z; acc[15] += w3*xv.w;
        }
        __syncthreads();
    }

    #pragma unroll
    for (int q = 0; q < 4; q++) {
        int v = vblk + vg*4 + q;
        float bias = W1b[v];
        #pragma unroll
        for (int p = 0; p < 4; p++) {
            int bb = bg*4 + p;
            out_pv[(size_t)bb*VOC + v] = acc[q*4 + p] + bias;
        }
    }
}

// ---------------- launch ----------------
extern "C" void kernel_launch(void* const* d_in, const int* in_sizes, int n_in,
                              void* d_out, int out_size)
{
    const int*   dec       = (const int*)  d_in[0];
    const int*   story     = (const int*)  d_in[1];
    const float* hidden    = (const float*)d_in[2];
    const int*   kb_values = (const int*)  d_in[3];
    const int*   kb_types  = (const int*)  d_in[4];
    // d_in[5] kb_fathers, d_in[6] kb_n_layers: tree is fully connected by
    // construction -> roots == per-tree sum; only needed for the ==0 bias
    // test which our exact root-sum reproduces.
    const float* C     = (const float*)d_in[7];
    const float* T_emb = (const float*)d_in[8];
    const float* Wq    = (const float*)d_in[9];
    const float* Wk    = (const float*)d_in[10];
    const float* Wv    = (const float*)d_in[11];
    const float* W1w   = (const float*)d_in[12];
    const float* W1b   = (const float*)d_in[13];
    const float* W_ih  = (const float*)d_in[14];
    const float* W_hh  = (const float*)d_in[15];
    const float* b_ih  = (const float*)d_in[16];
    const float* b_hh  = (const float*)d_in[17];

    float* out   = (float*)d_out;
    float* p_ptr = out;                      // (B, MM)
    float* p_voc = out + B*MM;               // (B, VOC)
    float* h_out = out + B*MM + (size_t)B*VOC; // (B, DIM)

    kB<<<B*NT, 256>>>(kb_values, kb_types, C, T_emb);             // heavy gather
    kA<<<B,    256>>>(dec, hidden, C, Wq, Wk, W_ih, W_hh, b_ih, b_hh, h_out);
    kD<<<B*MM, 64 >>>(story, C);
    kC<<<B,    256>>>(Wv);
    kE<<<B,    256>>>(p_ptr);
    kF<<<VOC/256, 256>>>(W1w, W1b, p_voc);
}

// round 3
// speedup vs baseline: 2.1707x; 2.1707x over previous
#include <cuda_runtime.h>
#include <cstddef>

#define B    16
#define NT   64
#define LN   256
#define LV   4
#define DIM  256
#define VOC  32000
#define MM   128
#define LS   4

// ---------------- scratch (device globals; no allocation) ----------------
__device__ __align__(16) float g_roots[B*NT*DIM];   // 1 MB
__device__ __align__(16) float g_kv  [B*DIM];
__device__ __align__(16) float g_hnew[B*DIM];
__device__ __align__(16) float g_u   [B*DIM];
__device__ __align__(16) float g_x512[B*2*DIM];     // [u | o0] per b
__device__ __align__(16) float g_M   [4*B*MM*DIM];  // 8 MB: sum_s C[k][story]
__device__ __align__(16) float g_gi  [B*3*DIM];
__device__ __align__(16) float g_gh  [B*3*DIM];
__device__ __align__(16) float g_q   [B*DIM];

__device__ __forceinline__ float warp_sum(float v) {
    #pragma unroll
    for (int o = 16; o; o >>= 1) v += __shfl_xor_sync(0xffffffffu, v, o);
    return v;
}
__device__ __forceinline__ float warp_max(float v) {
    #pragma unroll
    for (int o = 16; o; o >>= 1) v = fmaxf(v, __shfl_xor_sync(0xffffffffu, v, o));
    return v;
}

// ================= K1: fused front-end =================
// blocks [0,1024)        : roots gather (heavy, L2-bound — hides the rest)
// blocks [1024,1536)     : story sums (4 bm rows per block)
// blocks [1536,1664)     : input GEMVs: gi = x@W_ih.T+b_ih, gh = h@W_hh.T+b_hh, q = h@Wq.T
#define K1_ROOTS  1024
#define K1_STORY  512
#define K1_GEMV   128
__global__ __launch_bounds__(256) void K1(
    const int* __restrict__ kb_values, const int* __restrict__ kb_types,
    const float* __restrict__ C, const float* __restrict__ T_emb,
    const int* __restrict__ story,
    const int* __restrict__ dec, const float* __restrict__ hidden,
    const float* __restrict__ W_ih, const float* __restrict__ W_hh,
    const float* __restrict__ Wq,
    const float* __restrict__ b_ih, const float* __restrict__ b_hh)
{
    __shared__ union {
        struct { int vals[LN*LV]; int types[LN]; float4 part[3*64]; } rb;
        struct { float x[DIM]; float h[DIM]; } gv;
    } sh;

    int blk = blockIdx.x;
    int t   = threadIdx.x;

    if (blk < K1_ROOTS) {
        // ---- roots ----
        int bn = blk;
        int g  = t >> 6;
        int c  = t & 63;
        const int* vp = kb_values + (size_t)bn * LN * LV;
        for (int i = t; i < LN*LV; i += 256) sh.rb.vals[i] = vp[i];
        sh.rb.types[t] = kb_types[(size_t)bn*LN + t];
        __syncthreads();

        const float4* C0 = (const float4*)C;
        const float4* TE = (const float4*)T_emb;
        float4 acc = make_float4(0.f,0.f,0.f,0.f);
        for (int l = g; l < LN; l += 4) {
            int4 vv = *(const int4*)&sh.rb.vals[l*4];
            int  ty = sh.rb.types[l];
            float4 te = TE[(size_t)ty*64 + c];
            float4 a0 = C0[(size_t)vv.x*64 + c];
            float4 a1 = C0[(size_t)vv.y*64 + c];
            float4 a2 = C0[(size_t)vv.z*64 + c];
            float4 a3 = C0[(size_t)vv.w*64 + c];
            acc.x += te.x * ((a0.x+a1.x)+(a2.x+a3.x));
            acc.y += te.y * ((a0.y+a1.y)+(a2.y+a3.y));
            acc.z += te.z * ((a0.z+a1.z)+(a2.z+a3.z));
            acc.w += te.w * ((a0.w+a1.w)+(a2.w+a3.w));
        }
        if (g) sh.rb.part[(g-1)*64 + c] = acc;
        __syncthreads();
        if (!g) {
            float4 p0 = sh.rb.part[c], p1 = sh.rb.part[64+c], p2 = sh.rb.part[128+c];
            acc.x += p0.x+p1.x+p2.x;  acc.y += p0.y+p1.y+p2.y;
            acc.z += p0.z+p1.z+p2.z;  acc.w += p0.w+p1.w+p2.w;
            *(float4*)&g_roots[((size_t)bn*64 + c)*4] = acc;
        }
    } else if (blk < K1_ROOTS + K1_STORY) {
        // ---- story sums: 4 bm per block ----
        int bm = (blk - K1_ROOTS)*4 + (t >> 6);
        int c  = t & 63;
        const int* st = story + (size_t)bm*LS;
        int i0 = st[0], i1 = st[1], i2 = st[2], i3 = st[3];
        const float4* Cf = (const float4*)C;
        float4* Mf = (float4*)g_M;
        #pragma unroll
        for (int k = 0; k < 4; k++) {
            const float4* Ck = Cf + (size_t)k * VOC * 64;
            float4 a = Ck[(size_t)i0*64 + c];
            float4 b4= Ck[(size_t)i1*64 + c];
            float4 c4= Ck[(size_t)i2*64 + c];
            float4 d4= Ck[(size_t)i3*64 + c];
            float4 r;
            r.x=(a.x+b4.x)+(c4.x+d4.x); r.y=(a.y+b4.y)+(c4.y+d4.y);
            r.z=(a.z+b4.z)+(c4.z+d4.z); r.w=(a.w+b4.w)+(c4.w+d4.w);
            Mf[((size_t)k*B*MM + bm)*64 + c] = r;
        }
    } else {
        // ---- input GEMVs: 8 blocks per b, 224 outputs each ----
        int g2 = blk - (K1_ROOTS + K1_STORY);
        int b    = g2 >> 3;
        int part = g2 & 7;
        int w = t >> 5, lane = t & 31;

        if (t < DIM) {
            sh.gv.h[t] = hidden[b*DIM + t];
            sh.gv.x[t] = C[(size_t)dec[b]*DIM + t];
        }
        __syncthreads();
        const float4* x4 = (const float4*)sh.gv.x;
        const float4* h4 = (const float4*)sh.gv.h;

        int base = part*224;
        #pragma unroll 4
        for (int i = 0; i < 28; i++) {
            int o = base + w + 8*i;         // 0..1791
            const float* Wrow;
            const float4* v;
            if (o < 768)        { Wrow = W_ih + (size_t)o*DIM;        v = x4; }
            else if (o < 1536)  { Wrow = W_hh + (size_t)(o-768)*DIM;  v = h4; }
            else                { Wrow = Wq   + (size_t)(o-1536)*DIM; v = h4; }
            const float4* W4 = (const float4*)Wrow;
            float4 wa = W4[lane],      va = v[lane];
            float4 wb = W4[lane + 32], vb = v[lane + 32];
            float s = wa.x*va.x + wa.y*va.y + wa.z*va.z + wa.w*va.w
                    + wb.x*vb.x + wb.y*vb.y + wb.z*vb.z + wb.w*vb.w;
            s = warp_sum(s);
            if (lane == 0) {
                if (o < 768)       g_gi[b*768 + o]        = s + b_ih[o];
                else if (o < 1536) g_gh[b*768 + (o-768)]  = s + b_hh[o-768];
                else               g_q [b*DIM + (o-1536)] = s;
            }
        }
    }
}

// ================= K2: kv GEMV + GRU elementwise =================
__global__ __launch_bounds__(256) void K2(
    const float* __restrict__ Wk, const float* __restrict__ hidden,
    float* __restrict__ out_hnew)
{
    int b = blockIdx.x, t = threadIdx.x;
    __shared__ float s_q[DIM];
    s_q[t] = g_q[b*DIM + t];
    __syncthreads();

    float kv = 0.f;
    #pragma unroll 8
    for (int k = 0; k < DIM; k++) kv += Wk[(size_t)k*DIM + t] * s_q[k];
    g_kv[b*DIM + t] = kv;

    float gi0 = g_gi[b*768 + t], gh0 = g_gh[b*768 + t];
    float gi1 = g_gi[b*768 + DIM + t], gh1 = g_gh[b*768 + DIM + t];
    float gi2 = g_gi[b*768 + 2*DIM + t], gh2 = g_gh[b*768 + 2*DIM + t];
    float h   = hidden[b*DIM + t];
    float r  = 1.f / (1.f + __expf(-(gi0 + gh0)));
    float z  = 1.f / (1.f + __expf(-(gi1 + gh1)));
    float n  = tanhf(gi2 + r * gh2);
    float hn = (1.f - z) * n + z * h;
    g_hnew[b*DIM + t] = hn;
    out_hnew[b*DIM + t] = hn;
}

// ================= K3: attention over roots -> u =================
__global__ __launch_bounds__(512) void K3(const float* __restrict__ Wv)
{
    int b = blockIdx.x, t = threadIdx.x;
    int w = t >> 5, lane = t & 31;
    __shared__ float s_kv[DIM], s_sc[NT], s_p[2*DIM], s_rbar[DIM], s_feat[DIM];

    if (t < DIM) s_kv[t] = g_kv[b*DIM + t];
    __syncthreads();
    const float4* kv4 = (const float4*)s_kv;

    // scores + emptiness bias: 16 warps x 4 n
    #pragma unroll
    for (int i = 0; i < 4; i++) {
        int n = w + 16*i;
        const float4* r4 = (const float4*)(g_roots + ((size_t)b*NT + n)*DIM);
        float4 ra = r4[lane], ka = kv4[lane];
        float4 rb = r4[lane+32], kb = kv4[lane+32];
        float sc = ra.x*ka.x + ra.y*ka.y + ra.z*ka.z + ra.w*ka.w
                 + rb.x*kb.x + rb.y*kb.y + rb.z*kb.z + rb.w*kb.w;
        float rs = (ra.x+ra.y+ra.z+ra.w) + (rb.x+rb.y+rb.z+rb.w);
        sc = warp_sum(sc);
        rs = warp_sum(rs);
        if (lane == 0) s_sc[n] = (rs == 0.0f) ? sc - 1e9f : sc;
    }
    __syncthreads();

    if (t < 32) {
        float a = fmaxf(s_sc[t], s_sc[t+32]);
        a = warp_max(a);
        float e0 = __expf(s_sc[t]-a), e1 = __expf(s_sc[t+32]-a);
        float inv = 1.f / warp_sum(e0 + e1);
        s_sc[t] = e0*inv; s_sc[t+32] = e1*inv;
    }
    __syncthreads();

    // rbar: 512 threads, split n-range halves
    {
        int col = t & 255, half = t >> 8;
        float p = 0.f;
        #pragma unroll 8
        for (int n = half*32; n < half*32 + 32; n++)
            p += s_sc[n] * g_roots[((size_t)b*NT + n)*DIM + col];
        s_p[half*DIM + col] = p;
    }
    __syncthreads();
    if (t < DIM) s_rbar[t] = s_p[t] + s_p[DIM + t];
    __syncthreads();

    // feat = rbar @ Wv.T : 16 warps x 16 rows
    const float4* rb4 = (const float4*)s_rbar;
    #pragma unroll
    for (int i = 0; i < 16; i++) {
        int k = w + 16*i;
        const float4* W4 = (const float4*)(Wv + (size_t)k*DIM);
        float4 wa = W4[lane],    va = rb4[lane];
        float4 wb = W4[lane+32], vb = rb4[lane+32];
        float s = wa.x*va.x + wa.y*va.y + wa.z*va.z + wa.w*va.w
                + wb.x*vb.x + wb.y*vb.y + wb.z*vb.z + wb.w*vb.w;
        s = warp_sum(s);
        if (lane == 0) s_feat[k] = s;
    }
    __syncthreads();

    if (t < DIM) {
        float u = g_hnew[b*DIM + t] + s_feat[t];
        g_u[b*DIM + t] = u;
        g_x512[b*2*DIM + t] = u;
    }
}

// ================= K4: 3 memory hops =================
__global__ __launch_bounds__(512) void K4(float* __restrict__ out_pptr)
{
    int b = blockIdx.x, t = threadIdx.x;
    int w = t >> 5, lane = t & 31;
    __shared__ float s_u[DIM], s_l[MM], s_o[2*DIM];
    __shared__ float s_inv;

    if (t < DIM) s_u[t] = g_u[b*DIM + t];
    __syncthreads();

    for (int hop = 0; hop < 3; hop++) {
        const float* MA = g_M + ((size_t)hop*B + b)*MM*DIM;
        const float4* u4 = (const float4*)s_u;
        #pragma unroll
        for (int i = 0; i < 8; i++) {
            int m = w + 16*i;
            const float4* r4 = (const float4*)(MA + (size_t)m*DIM);
            float4 ra = r4[lane],    ua = u4[lane];
            float4 rb = r4[lane+32], ub = u4[lane+32];
            float s = ra.x*ua.x + ra.y*ua.y + ra.z*ua.z + ra.w*ua.w
                    + rb.x*ub.x + rb.y*ub.y + rb.z*ub.z + rb.w*ub.w;
            s = warp_sum(s);
            if (lane == 0) s_l[m] = s;
        }
        __syncthreads();

        if (hop == 2) {
            if (t < MM) out_pptr[b*MM + t] = s_l[t];
            return;
        }

        if (t < 32) {
            float a = -1e30f, e[4];
            #pragma unroll
            for (int q = 0; q < 4; q++) a = fmaxf(a, s_l[t + 32*q]);
            a = warp_max(a);
            float sm = 0.f;
            #pragma unroll
            for (int q = 0; q < 4; q++) { e[q] = __expf(s_l[t+32*q]-a); sm += e[q]; }
            sm = warp_sum(sm);
            #pragma unroll
            for (int q = 0; q < 4; q++) s_l[t + 32*q] = e[q];
            if (t == 0) s_inv = 1.f / sm;
        }
        __syncthreads();

        const float* MC = g_M + ((size_t)(hop+1)*B + b)*MM*DIM;
        {
            int col = t & 255, half = t >> 8;
            float p = 0.f;
            #pragma unroll 8
            for (int m = half*64; m < half*64 + 64; m++)
                p += s_l[m] * MC[(size_t)m*DIM + col];
            s_o[half*DIM + col] = p;
        }
        __syncthreads();
        if (t < DIM) {
            float o = (s_o[t] + s_o[DIM + t]) * s_inv;
            if (hop == 0) g_x512[b*2*DIM + DIM + t] = o;
            s_u[t] += o;
        }
        __syncthreads();
    }
}

// ================= K5: p_vocab = [u|o] @ W1_w.T + b =================
__global__ __launch_bounds__(256) void K5(
    const float* __restrict__ W1w, const float* __restrict__ W1b,
    float* __restrict__ out_pv)
{
    __shared__ float W_s[256*33];
    __shared__ float x_s[32*16];

    int t = threadIdx.x;
    int vblk = blockIdx.x * 256;
    int bg = t & 3;
    int vg = t >> 2;
    int ljq = t & 7, lvb = t >> 3;

    float acc[16];
    #pragma unroll
    for (int i = 0; i < 16; i++) acc[i] = 0.f;

    for (int ch = 0; ch < 16; ch++) {
        int j0 = ch * 32;
        #pragma unroll
        for (int v = lvb; v < 256; v += 32) {
            float4 gw = *(const float4*)&W1w[(size_t)(vblk + v)*512 + j0 + ljq*4];
            int base = v*33 + ljq*4;
            W_s[base+0]=gw.x; W_s[base+1]=gw.y; W_s[base+2]=gw.z; W_s[base+3]=gw.w;
        }
        {
            int i = t;
            #pragma unroll
            for (int rep = 0; rep < 2; rep++, i += 256) {
                int jj = i >> 4, bb = i & 15;
                x_s[jj*16 + bb] = g_x512[bb*2*DIM + j0 + jj];
            }
        }
        __syncthreads();

        #pragma unroll
        for (int j = 0; j < 32; j++) {
            float4 xv = *(const float4*)&x_s[j*16 + bg*4];
            float w0 = W_s[(vg*4+0)*33 + j];
            float w1 = W_s[(vg*4+1)*33 + j];
            float w2 = W_s[(vg*4+2)*33 + j];
            float w3 = W_s[(vg*4+3)*33 + j];
            acc[ 0]+=w0*xv.x; acc[ 1]+=w0*xv.y; acc[ 2]+=w0*xv.z; acc[ 3]+=w0*xv.w;
            acc[ 4]+=w1*xv.x; acc[ 5]+=w1*xv.y; acc[ 6]+=w1*xv.z; acc[ 7]+=w1*xv.w;
            acc[ 8]+=w2*xv.x; acc[ 9]+=w2*xv.y; acc[10]+=w2*xv.z; acc[11]+=w2*xv.w;
            acc[12]+=w3*xv.x; acc[13]+=w3*xv.y; acc[14]+=w3*xv.z; acc[15]+=w3*xv.w;
        }
        __syncthreads();
    }

    #pragma unroll
    for (int q = 0; q < 4; q++) {
        int v = vblk + vg*4 + q;
        float bias = W1b[v];
        #pragma unroll
        for (int p = 0; p < 4; p++)
            out_pv[(size_t)(bg*4+p)*VOC + v] = acc[q*4 + p] + bias;
    }
}

// ================= launch =================
extern "C" void kernel_launch(void* const* d_in, const int* in_sizes, int n_in,
                              void* d_out, int out_size)
{
    const int*   dec       = (const int*)  d_in[0];
    const int*   story     = (const int*)  d_in[1];
    const float* hidden    = (const float*)d_in[2];
    const int*   kb_values = (const int*)  d_in[3];
    const int*   kb_types  = (const int*)  d_in[4];
    const float* C     = (const float*)d_in[7];
    const float* T_emb = (const float*)d_in[8];
    const float* Wq    = (const float*)d_in[9];
    const float* Wk    = (const float*)d_in[10];
    const float* Wv    = (const float*)d_in[11];
    const float* W1w   = (const float*)d_in[12];
    const float* W1b   = (const float*)d_in[13];
    const float* W_ih  = (const float*)d_in[14];
    const float* W_hh  = (const float*)d_in[15];
    const float* b_ih  = (const float*)d_in[16];
    const float* b_hh  = (const float*)d_in[17];

    float* out   = (float*)d_out;
    float* p_ptr = out;
    float* p_voc = out + B*MM;
    float* h_out = out + B*MM + (size_t)B*VOC;

    K1<<<K1_ROOTS + K1_STORY + K1_GEMV, 256>>>(
        kb_values, kb_types, C, T_emb, story, dec, hidden,
        W_ih, W_hh, Wq, b_ih, b_hh);
    K2<<<B, 256>>>(Wk, hidden, h_out);
    K3<<<B, 512>>>(Wv);
    K4<<<B, 512>>>(p_ptr);
    K5<<<VOC/256, 256>>>(W1w, W1b, p_voc);
}

// round 5
// speedup vs baseline: 2.5147x; 1.1585x over previous
#include <cuda_runtime.h>
#include <cstddef>

#define B    16
#define NT   64
#define LN   256
#define LV   4
#define DIM  256
#define VOC  32000
#define MM   128
#define LS   4

// ---------------- scratch (device globals; no allocation) ----------------
__device__ __align__(16) float g_roots[B*NT*DIM];   // 1 MB
__device__ __align__(16) float g_u   [B*DIM];
__device__ __align__(16) float g_x512[B*2*DIM];     // [u | o0] per b
__device__ __align__(16) float g_M   [4*B*MM*DIM];  // 8 MB: sum_s C[k][story]
__device__ __align__(16) float g_gi  [B*3*DIM];
__device__ __align__(16) float g_gh  [B*3*DIM];
__device__ __align__(16) float g_q   [B*DIM];

__device__ __forceinline__ float warp_sum(float v) {
    #pragma unroll
    for (int o = 16; o; o >>= 1) v += __shfl_xor_sync(0xffffffffu, v, o);
    return v;
}
__device__ __forceinline__ float warp_max(float v) {
    #pragma unroll
    for (int o = 16; o; o >>= 1) v = fmaxf(v, __shfl_xor_sync(0xffffffffu, v, o));
    return v;
}

// f32x2 packed helpers (Blackwell dual-FMA pipe)
__device__ __forceinline__ unsigned long long pack2(float a, float b) {
    unsigned long long r;
    asm("mov.b64 %0, {%1, %2};" : "=l"(r) : "f"(a), "f"(b));
    return r;
}
__device__ __forceinline__ void fma2(unsigned long long& d, unsigned long long a, unsigned long long b) {
    asm("fma.rn.f32x2 %0, %1, %2, %0;" : "+l"(d) : "l"(a), "l"(b));
}
__device__ __forceinline__ void unpack2(unsigned long long v, float& lo, float& hi) {
    asm("mov.b64 {%0, %1}, %2;" : "=f"(lo), "=f"(hi) : "l"(v));
}

// ================= K1: fused front-end =================
#define K1_ROOTS  1024
#define K1_STORY  512
#define K1_GEMV   128
__global__ __launch_bounds__(256) void K1(
    const int* __restrict__ kb_values, const int* __restrict__ kb_types,
    const float* __restrict__ C, const float* __restrict__ T_emb,
    const int* __restrict__ story,
    const int* __restrict__ dec, const float* __restrict__ hidden,
    const float* __restrict__ W_ih, const float* __restrict__ W_hh,
    const float* __restrict__ Wq,
    const float* __restrict__ b_ih, const float* __restrict__ b_hh)
{
    __shared__ union {
        struct { int vals[LN*LV]; int types[LN]; float4 part[3*64]; } rb;
        struct { float x[DIM]; float h[DIM]; } gv;
    } sh;

    int blk = blockIdx.x;
    int t   = threadIdx.x;

    if (blk < K1_ROOTS) {
        // ---- roots gather: C0 via L2-only loads, T_emb stays L1-resident ----
        int bn = blk;
        int g  = t >> 6;
        int c  = t & 63;
        const int* vp = kb_values + (size_t)bn * LN * LV;
        for (int i = t; i < LN*LV; i += 256) sh.rb.vals[i] = vp[i];
        sh.rb.types[t] = kb_types[(size_t)bn*LN + t];
        __syncthreads();

        const float4* C0 = (const float4*)C;
        const float4* TE = (const float4*)T_emb;
        float4 acc = make_float4(0.f,0.f,0.f,0.f);
        #pragma unroll 4
        for (int l = g; l < LN; l += 4) {
            int4 vv = *(const int4*)&sh.rb.vals[l*4];
            int  ty = sh.rb.types[l];
            float4 te = TE[(size_t)ty*64 + c];                 // .ca -> L1 hot
            float4 a0 = __ldcg(&C0[(size_t)vv.x*64 + c]);      // L2-only
            float4 a1 = __ldcg(&C0[(size_t)vv.y*64 + c]);
            float4 a2 = __ldcg(&C0[(size_t)vv.z*64 + c]);
            float4 a3 = __ldcg(&C0[(size_t)vv.w*64 + c]);
            acc.x += te.x * ((a0.x+a1.x)+(a2.x+a3.x));
            acc.y += te.y * ((a0.y+a1.y)+(a2.y+a3.y));
            acc.z += te.z * ((a0.z+a1.z)+(a2.z+a3.z));
            acc.w += te.w * ((a0.w+a1.w)+(a2.w+a3.w));
        }
        if (g) sh.rb.part[(g-1)*64 + c] = acc;
        __syncthreads();
        if (!g) {
            float4 p0 = sh.rb.part[c], p1 = sh.rb.part[64+c], p2 = sh.rb.part[128+c];
            acc.x += p0.x+p1.x+p2.x;  acc.y += p0.y+p1.y+p2.y;
            acc.z += p0.z+p1.z+p2.z;  acc.w += p0.w+p1.w+p2.w;
            *(float4*)&g_roots[((size_t)bn*64 + c)*4] = acc;
        }
    } else if (blk < K1_ROOTS + K1_STORY) {
        // ---- story sums: 4 bm per block ----
        int bm = (blk - K1_ROOTS)*4 + (t >> 6);
        int c  = t & 63;
        const int* st = story + (size_t)bm*LS;
        int i0 = st[0], i1 = st[1], i2 = st[2], i3 = st[3];
        const float4* Cf = (const float4*)C;
        float4* Mf = (float4*)g_M;
        #pragma unroll
        for (int k = 0; k < 4; k++) {
            const float4* Ck = Cf + (size_t)k * VOC * 64;
            float4 a  = __ldcg(&Ck[(size_t)i0*64 + c]);
            float4 b4 = __ldcg(&Ck[(size_t)i1*64 + c]);
            float4 c4 = __ldcg(&Ck[(size_t)i2*64 + c]);
            float4 d4 = __ldcg(&Ck[(size_t)i3*64 + c]);
            float4 r;
            r.x=(a.x+b4.x)+(c4.x+d4.x); r.y=(a.y+b4.y)+(c4.y+d4.y);
            r.z=(a.z+b4.z)+(c4.z+d4.z); r.w=(a.w+b4.w)+(c4.w+d4.w);
            Mf[((size_t)k*B*MM + bm)*64 + c] = r;
        }
    } else {
        // ---- input GEMVs: 8 blocks per b, 224 outputs each ----
        int g2 = blk - (K1_ROOTS + K1_STORY);
        int b    = g2 >> 3;
        int part = g2 & 7;
        int w = t >> 5, lane = t & 31;

        if (t < DIM) {
            sh.gv.h[t] = hidden[b*DIM + t];
            sh.gv.x[t] = C[(size_t)dec[b]*DIM + t];
        }
        __syncthreads();
        const float4* x4 = (const float4*)sh.gv.x;
        const float4* h4 = (const float4*)sh.gv.h;

        int base = part*224;
        #pragma unroll 4
        for (int i = 0; i < 28; i++) {
            int o = base + w + 8*i;         // 0..1791
            const float* Wrow;
            const float4* v;
            if (o < 768)        { Wrow = W_ih + (size_t)o*DIM;        v = x4; }
            else if (o < 1536)  { Wrow = W_hh + (size_t)(o-768)*DIM;  v = h4; }
            else                { Wrow = Wq   + (size_t)(o-1536)*DIM; v = h4; }
            const float4* W4 = (const float4*)Wrow;
            float4 wa = W4[lane],      va = v[lane];
            float4 wb = W4[lane + 32], vb = v[lane + 32];
            float s = wa.x*va.x + wa.y*va.y + wa.z*va.z + wa.w*va.w
                    + wb.x*vb.x + wb.y*vb.y + wb.z*vb.z + wb.w*vb.w;
            s = warp_sum(s);
            if (lane == 0) {
                if (o < 768)       g_gi[b*768 + o]        = s + b_ih[o];
                else if (o < 1536) g_gh[b*768 + (o-768)]  = s + b_hh[o-768];
                else               g_q [b*DIM + (o-1536)] = s;
            }
        }
    }
}

// ================= K23: kv GEMV + GRU + attention over roots =================
__global__ __launch_bounds__(512) void K23(
    const float* __restrict__ Wk, const float* __restrict__ hidden,
    const float* __restrict__ Wv, float* __restrict__ out_hnew)
{
    int b = blockIdx.x, t = threadIdx.x;
    int w = t >> 5, lane = t & 31;
    __shared__ float s_q[DIM], s_kv[DIM], s_hn[DIM], s_sc[NT],
                     s_p[2*DIM], s_rbar[DIM], s_feat[DIM];

    if (t < DIM) s_q[t] = g_q[b*DIM + t];
    __syncthreads();

    // kv = Wk.T @ q : split k-range across thread halves
    {
        int col = t & 255, half = t >> 8;
        float p = 0.f;
        #pragma unroll 8
        for (int k = half*128; k < half*128 + 128; k++)
            p += Wk[(size_t)k*DIM + col] * s_q[k];
        s_p[half*DIM + col] = p;
    }
    __syncthreads();
    if (t < DIM) {
        s_kv[t] = s_p[t] + s_p[DIM + t];
        // GRU elementwise
        float gi0 = g_gi[b*768 + t],         gh0 = g_gh[b*768 + t];
        float gi1 = g_gi[b*768 + DIM + t],   gh1 = g_gh[b*768 + DIM + t];
        float gi2 = g_gi[b*768 + 2*DIM + t], gh2 = g_gh[b*768 + 2*DIM + t];
        float h   = hidden[b*DIM + t];
        float r  = 1.f / (1.f + __expf(-(gi0 + gh0)));
        float z  = 1.f / (1.f + __expf(-(gi1 + gh1)));
        float n  = tanhf(gi2 + r * gh2);
        float hn = (1.f - z) * n + z * h;
        s_hn[t] = hn;
        out_hnew[b*DIM + t] = hn;
    }
    __syncthreads();

    const float4* kv4 = (const float4*)s_kv;
    // scores + emptiness bias: 16 warps x 4 n
    #pragma unroll
    for (int i = 0; i < 4; i++) {
        int n = w + 16*i;
        const float4* r4 = (const float4*)(g_roots + ((size_t)b*NT + n)*DIM);
        float4 ra = r4[lane], ka = kv4[lane];
        float4 rb = r4[lane+32], kb = kv4[lane+32];
        float sc = ra.x*ka.x + ra.y*ka.y + ra.z*ka.z + ra.w*ka.w
                 + rb.x*kb.x + rb.y*kb.y + rb.z*kb.z + rb.w*kb.w;
        float rs = (ra.x+ra.y+ra.z+ra.w) + (rb.x+rb.y+rb.z+rb.w);
        sc = warp_sum(sc);
        rs = warp_sum(rs);
        if (lane == 0) s_sc[n] = (rs == 0.0f) ? sc - 1e9f : sc;
    }
    __syncthreads();

    if (t < 32) {
        float a = fmaxf(s_sc[t], s_sc[t+32]);
        a = warp_max(a);
        float e0 = __expf(s_sc[t]-a), e1 = __expf(s_sc[t+32]-a);
        float inv = 1.f / warp_sum(e0 + e1);
        s_sc[t] = e0*inv; s_sc[t+32] = e1*inv;
    }
    __syncthreads();

    // rbar
    {
        int col = t & 255, half = t >> 8;
        float p = 0.f;
        #pragma unroll 8
        for (int n = half*32; n < half*32 + 32; n++)
            p += s_sc[n] * g_roots[((size_t)b*NT + n)*DIM + col];
        s_p[half*DIM + col] = p;
    }
    __syncthreads();
    if (t < DIM) s_rbar[t] = s_p[t] + s_p[DIM + t];
    __syncthreads();

    // feat = rbar @ Wv.T : 16 warps x 16 rows
    const float4* rb4 = (const float4*)s_rbar;
    #pragma unroll
    for (int i = 0; i < 16; i++) {
        int k = w + 16*i;
        const float4* W4 = (const float4*)(Wv + (size_t)k*DIM);
        float4 wa = W4[lane],    va = rb4[lane];
        float4 wb = W4[lane+32], vb = rb4[lane+32];
        float s = wa.x*va.x + wa.y*va.y + wa.z*va.z + wa.w*va.w
                + wb.x*vb.x + wb.y*vb.y + wb.z*vb.z + wb.w*vb.w;
        s = warp_sum(s);
        if (lane == 0) s_feat[k] = s;
    }
    __syncthreads();

    if (t < DIM) {
        float u = s_hn[t] + s_feat[t];
        g_u[b*DIM + t] = u;
        g_x512[b*2*DIM + t] = u;
    }
}

// ================= K4: 3 memory hops (1024 threads, 4 rows/warp) ===========
__global__ __launch_bounds__(1024) void K4(float* __restrict__ out_pptr)
{
    int b = blockIdx.x, t = threadIdx.x;
    int w = t >> 5, lane = t & 31;
    __shared__ float s_u[DIM], s_l[MM], s_o[4*DIM];
    __shared__ float s_inv;

    if (t < DIM) s_u[t] = g_u[b*DIM + t];
    __syncthreads();

    for (int hop = 0; hop < 3; hop++) {
        const float* MA = g_M + ((size_t)hop*B + b)*MM*DIM;
        const float4* u4 = (const float4*)s_u;
        {
            int m0 = w*4;
            float4 ua = u4[lane], ub = u4[lane+32];
            const float4* r0 = (const float4*)(MA + (size_t)(m0+0)*DIM);
            const float4* r1 = (const float4*)(MA + (size_t)(m0+1)*DIM);
            const float4* r2 = (const float4*)(MA + (size_t)(m0+2)*DIM);
            const float4* r3 = (const float4*)(MA + (size_t)(m0+3)*DIM);
            float4 v0 = r0[lane], v1 = r1[lane], v2 = r2[lane], v3 = r3[lane];
            float a0 = v0.x*ua.x + v0.y*ua.y + v0.z*ua.z + v0.w*ua.w;
            float a1 = v1.x*ua.x + v1.y*ua.y + v1.z*ua.z + v1.w*ua.w;
            float a2 = v2.x*ua.x + v2.y*ua.y + v2.z*ua.z + v2.w*ua.w;
            float a3 = v3.x*ua.x + v3.y*ua.y + v3.z*ua.z + v3.w*ua.w;
            v0 = r0[lane+32]; v1 = r1[lane+32]; v2 = r2[lane+32]; v3 = r3[lane+32];
            a0 += v0.x*ub.x + v0.y*ub.y + v0.z*ub.z + v0.w*ub.w;
            a1 += v1.x*ub.x + v1.y*ub.y + v1.z*ub.z + v1.w*ub.w;
            a2 += v2.x*ub.x + v2.y*ub.y + v2.z*ub.z + v2.w*ub.w;
            a3 += v3.x*ub.x + v3.y*ub.y + v3.z*ub.z + v3.w*ub.w;
            a0 = warp_sum(a0); a1 = warp_sum(a1);
            a2 = warp_sum(a2); a3 = warp_sum(a3);
            if (lane == 0) {
                s_l[m0+0] = a0; s_l[m0+1] = a1;
                s_l[m0+2] = a2; s_l[m0+3] = a3;
            }
        }
        __syncthreads();

        if (hop == 2) {
            if (t < MM) out_pptr[b*MM + t] = s_l[t];
            return;
        }

        if (t < 32) {
            float a = -1e30f, e[4];
            #pragma unroll
            for (int q = 0; q < 4; q++) a = fmaxf(a, s_l[t + 32*q]);
            a = warp_max(a);
            float sm = 0.f;
            #pragma unroll
            for (int q = 0; q < 4; q++) { e[q] = __expf(s_l[t+32*q]-a); sm += e[q]; }
            sm = warp_sum(sm);
            #pragma unroll
            for (int q = 0; q < 4; q++) s_l[t + 32*q] = e[q];
            if (t == 0) s_inv = 1.f / sm;
        }
        __syncthreads();

        const float* MC = g_M + ((size_t)(hop+1)*B + b)*MM*DIM;
        {
            int col = t & 255, q = t >> 8;     // q = 0..3
            float p = 0.f;
            #pragma unroll 8
            for (int m = q*32; m < q*32 + 32; m++)
                p += s_l[m] * MC[(size_t)m*DIM + col];
            s_o[q*DIM + col] = p;
        }
        __syncthreads();
        if (t < DIM) {
            float o = (s_o[t] + s_o[DIM+t] + s_o[2*DIM+t] + s_o[3*DIM+t]) * s_inv;
            if (hop == 0) g_x512[b*2*DIM + DIM + t] = o;
            s_u[t] += o;
        }
        __syncthreads();
    }
}

// ================= K5: p_vocab = [u|o] @ W1_w.T + b  (f32x2 core) ==========
__global__ __launch_bounds__(256) void K5(
    const float* __restrict__ W1w, const float* __restrict__ W1b,
    float* __restrict__ out_pv)
{
    __shared__ float W_s[256*33];
    __shared__ __align__(16) float x_s[32*16];

    int t = threadIdx.x;
    int vblk = blockIdx.x * 256;
    int bg = t & 3;
    int vg = t >> 2;
    int ljq = t & 7, lvb = t >> 3;

    unsigned long long acc2[8];   // [q][bpair]
    #pragma unroll
    for (int i = 0; i < 8; i++) acc2[i] = pack2(0.f, 0.f);

    for (int ch = 0; ch < 16; ch++) {
        int j0 = ch * 32;
        #pragma unroll
        for (int v = lvb; v < 256; v += 32) {
            float4 gw = *(const float4*)&W1w[(size_t)(vblk + v)*512 + j0 + ljq*4];
            int base = v*33 + ljq*4;
            W_s[base+0]=gw.x; W_s[base+1]=gw.y; W_s[base+2]=gw.z; W_s[base+3]=gw.w;
        }
        {
            int i = t;
            #pragma unroll
            for (int rep = 0; rep < 2; rep++, i += 256) {
                int jj = i >> 4, bb = i & 15;
                x_s[jj*16 + bb] = g_x512[bb*2*DIM + j0 + jj];
            }
        }
        __syncthreads();

        #pragma unroll
        for (int j = 0; j < 32; j++) {
            // x pairs come packed for free from the [j][b] layout
            ulonglong2 xp = *(const ulonglong2*)&x_s[j*16 + bg*4];
            float w0 = W_s[(vg*4+0)*33 + j];
            float w1 = W_s[(vg*4+1)*33 + j];
            float w2 = W_s[(vg*4+2)*33 + j];
            float w3 = W_s[(vg*4+3)*33 + j];
            unsigned long long w0p = pack2(w0,w0), w1p = pack2(w1,w1);
            unsigned long long w2p = pack2(w2,w2), w3p = pack2(w3,w3);
            fma2(acc2[0], w0p, xp.x);  fma2(acc2[1], w0p, xp.y);
            fma2(acc2[2], w1p, xp.x);  fma2(acc2[3], w1p, xp.y);
            fma2(acc2[4], w2p, xp.x);  fma2(acc2[5], w2p, xp.y);
            fma2(acc2[6], w3p, xp.x);  fma2(acc2[7], w3p, xp.y);
        }
        __syncthreads();
    }

    #pragma unroll
    for (int q = 0; q < 4; q++) {
        int v = vblk + vg*4 + q;
        float bias = W1b[v];
        float p0, p1, p2, p3;
        unpack2(acc2[q*2+0], p0, p1);
        unpack2(acc2[q*2+1], p2, p3);
        out_pv[(size_t)(bg*4+0)*VOC + v] = p0 + bias;
        out_pv[(size_t)(bg*4+1)*VOC + v] = p1 + bias;
        out_pv[(size_t)(bg*4+2)*VOC + v] = p2 + bias;
        out_pv[(size_t)(bg*4+3)*VOC + v] = p3 + bias;
    }
}

// ================= launch =================
extern "C" void kernel_launch(void* const* d_in, const int* in_sizes, int n_in,
                              void* d_out, int out_size)
{
    const int*   dec       = (const int*)  d_in[0];
    const int*   story     = (const int*)  d_in[1];
    const float* hidden    = (const float*)d_in[2];
    const int*   kb_values = (const int*)  d_in[3];
    const int*   kb_types  = (const int*)  d_in[4];
    const float* C     = (const float*)d_in[7];
    const float* T_emb = (const float*)d_in[8];
    const float* Wq    = (const float*)d_in[9];
    const float* Wk    = (const float*)d_in[10];
    const float* Wv    = (const float*)d_in[11];
    const float* W1w   = (const float*)d_in[12];
    const float* W1b   = (const float*)d_in[13];
    const float* W_ih  = (const float*)d_in[14];
    const float* W_hh  = (const float*)d_in[15];
    const float* b_ih  = (const float*)d_in[16];
    const float* b_hh  = (const float*)d_in[17];

    float* out   = (float*)d_out;
    float* p_ptr = out;
    float* p_voc = out + B*MM;
    float* h_out = out + B*MM + (size_t)B*VOC;

    K1<<<K1_ROOTS + K1_STORY + K1_GEMV, 256>>>(
        kb_values, kb_types, C, T_emb, story, dec, hidden,
        W_ih, W_hh, Wq, b_ih, b_hh);
    K23<<<B, 512>>>(Wk, hidden, Wv, h_out);
    K4<<<B, 1024>>>(p_ptr);
    K5<<<VOC/256, 256>>>(W1w, W1b, p_voc);
}